// round 5
// baseline (speedup 1.0000x reference)
#include <cuda_runtime.h>

// Problem constants
#define BB   4
#define CC   256
#define GG   16
#define KF   7      // filter K
#define PP   3
#define HH   56
#define WW   56
#define HW   (HH*WW)          // 3136
#define CR   64               // C / R
#define CPG  16               // C / G
#define KK2  49               // K*K

// Scratch for h = reduce(x): [B][CR][HW] fp32 = 3.2 MB
__device__ float g_h[BB * CR * HW];

// ---------------------------------------------------------------------------
// Kernel 1: h[b][o][p] = sum_c reduce_w[o][c] * x[b][c][p] + reduce_b[o]
// Block: 256 threads, tile of 64 pixels, all 64 outputs.
// Thread computes 4 outputs x 4 pixels (float4 along pixels).
// ---------------------------------------------------------------------------
__global__ __launch_bounds__(256) void reduce_kernel(
    const float* __restrict__ x,
    const float* __restrict__ rw,
    const float* __restrict__ rb)
{
    __shared__ float sx[64 * 64];    // [c_chunk][px]
    __shared__ float srw[64 * 64];   // [o][c_chunk]

    const int b   = blockIdx.y;
    const int px0 = blockIdx.x * 64;
    const int tid = threadIdx.x;
    const int pxq = tid & 15;        // pixel quad (4 px)
    const int o0  = (tid >> 4) * 4;  // 4 outputs

    float acc[4][4];
#pragma unroll
    for (int i = 0; i < 4; i++)
#pragma unroll
        for (int j = 0; j < 4; j++) acc[i][j] = 0.f;

    for (int cc0 = 0; cc0 < CC; cc0 += 64) {
        // stage x chunk: [64 c][64 px], coalesced 64-float rows
        for (int i = tid; i < 64 * 64; i += 256) {
            int c = i >> 6, p = i & 63;
            sx[i] = x[(b * CC + cc0 + c) * HW + px0 + p];
        }
        // stage weight chunk: [64 o][64 c], coalesced along c
        for (int i = tid; i < 64 * 64; i += 256) {
            int o = i >> 6, c = i & 63;
            srw[i] = rw[o * CC + cc0 + c];
        }
        __syncthreads();

#pragma unroll 4
        for (int c = 0; c < 64; c++) {
            float4 xv = reinterpret_cast<const float4*>(sx + c * 64)[pxq];
#pragma unroll
            for (int j = 0; j < 4; j++) {
                float w = srw[(o0 + j) * 64 + c];
                acc[j][0] += w * xv.x;
                acc[j][1] += w * xv.y;
                acc[j][2] += w * xv.z;
                acc[j][3] += w * xv.w;
            }
        }
        __syncthreads();
    }

#pragma unroll
    for (int j = 0; j < 4; j++) {
        float bias = rb[o0 + j];
        float4 v = make_float4(acc[j][0] + bias, acc[j][1] + bias,
                               acc[j][2] + bias, acc[j][3] + bias);
        reinterpret_cast<float4*>(g_h + (b * CR + o0 + j) * HW + px0)[pxq] = v;
    }
}

// ---------------------------------------------------------------------------
// Kernel 2: fused span GEMM + involution.
// Grid: (7, 7, B*G). Block handles one 8x8 output tile for one (batch, group):
//   - load h tile [64 ch][64 px] into shared
//   - load x patch [16 ch][14x14] (with halo, zero padded) into shared
//   - compute kern[49][64 px] = span_w_g @ h + bias, entirely in shared
//   - out[ch][px] = sum_kk kern[kk][px] * xpatch[ch][py+kh][px+kw]
// kern never touches HBM (saves ~80 MB of traffic).
// ---------------------------------------------------------------------------
__global__ __launch_bounds__(256) void invol_kernel(
    const float* __restrict__ x,
    const float* __restrict__ sw,
    const float* __restrict__ sb,
    float* __restrict__ out)
{
    __shared__ float sh_h[64 * 64];          // 16 KB
    __shared__ float sh_k[KK2 * 64];         // 12.25 KB
    __shared__ float sh_x[CPG * 14 * 17];    // 14.9 KB (row stride 17: bank spread)

    const int bz  = blockIdx.z;
    const int b   = bz >> 4;
    const int g   = bz & 15;
    const int ty0 = blockIdx.y * 8;
    const int tx0 = blockIdx.x * 8;
    const int tid = threadIdx.x;

    // phase 1: h tile [64 ch][64 px]
    for (int i = tid; i < 64 * 64; i += 256) {
        int c  = i >> 6, px = i & 63;
        int ly = px >> 3, lx = px & 7;
        sh_h[i] = g_h[(b * CR + c) * HW + (ty0 + ly) * WW + tx0 + lx];
    }
    // phase 1b: x patch, 16 ch x 14x14 with zero-padded halo
    for (int i = tid; i < CPG * 14 * 14; i += 256) {
        int ch = i / 196;
        int r2 = i % 196;
        int r = r2 / 14, cw = r2 % 14;
        int gy = ty0 + r - PP, gx = tx0 + cw - PP;
        float v = 0.f;
        if (gy >= 0 && gy < HH && gx >= 0 && gx < WW)
            v = x[((b * CC + g * CPG + ch) * HH + gy) * WW + gx];
        sh_x[(ch * 14 + r) * 17 + cw] = v;
    }
    __syncthreads();

    // phase 2: kern[kk][px] = sum_c span_w[g*49+kk][c] * h[c][px] + sb
    const float* swg = sw + (g * KK2) * CR;
#pragma unroll
    for (int it = 0; it < 4; it++) {
        int idx = tid + it * 256;
        if (idx < KK2 * 16) {
            int kk = idx >> 4, pxq = idx & 15;
            float bias = sb[g * KK2 + kk];
            float a0 = bias, a1 = bias, a2 = bias, a3 = bias;
            const float* wrow = swg + kk * CR;
#pragma unroll 4
            for (int c = 0; c < CR; c++) {
                float  w  = wrow[c];
                float4 hv = reinterpret_cast<const float4*>(sh_h + c * 64)[pxq];
                a0 += w * hv.x; a1 += w * hv.y;
                a2 += w * hv.z; a3 += w * hv.w;
            }
            reinterpret_cast<float4*>(sh_k + kk * 64)[pxq] =
                make_float4(a0, a1, a2, a3);
        }
    }
    __syncthreads();

    // phase 3: involution. Thread: (ch, 4-px quad). 16 ch x 16 quads = 256.
    const int ch  = tid >> 4;
    const int pxq = tid & 15;
    const int ly  = pxq >> 1;
    const int lx  = (pxq & 1) * 4;

    float acc0 = 0.f, acc1 = 0.f, acc2 = 0.f, acc3 = 0.f;
#pragma unroll
    for (int kh = 0; kh < KF; kh++) {
        float xr[10];
        const float* xrow = sh_x + (ch * 14 + ly + kh) * 17 + lx;
#pragma unroll
        for (int j = 0; j < 10; j++) xr[j] = xrow[j];
#pragma unroll
        for (int kw = 0; kw < KF; kw++) {
            float4 kv = reinterpret_cast<const float4*>(sh_k + (kh * KF + kw) * 64)[pxq];
            acc0 += kv.x * xr[kw + 0];
            acc1 += kv.y * xr[kw + 1];
            acc2 += kv.z * xr[kw + 2];
            acc3 += kv.w * xr[kw + 3];
        }
    }

    float4 ov = make_float4(acc0, acc1, acc2, acc3);
    reinterpret_cast<float4*>(
        out + ((b * CC + g * CPG + ch) * HH + ty0 + ly) * WW + tx0 + lx)[0] = ov;
}

// ---------------------------------------------------------------------------
extern "C" void kernel_launch(void* const* d_in, const int* in_sizes, int n_in,
                              void* d_out, int out_size)
{
    const float* x  = (const float*)d_in[0];  // (4,256,56,56)
    const float* rw = (const float*)d_in[1];  // (64,256)
    const float* rb = (const float*)d_in[2];  // (64,)
    const float* sw = (const float*)d_in[3];  // (784,64)
    const float* sb = (const float*)d_in[4];  // (784,)
    float* out = (float*)d_out;               // (4,256,56,56)

    reduce_kernel<<<dim3(HW / 64, BB), 256>>>(x, rw, rb);
    invol_kernel<<<dim3(WW / 8, HH / 8, BB * GG), 256>>>(x, sw, sb, out);
}

// round 9
// speedup vs baseline: 2.5673x; 2.5673x over previous
#include <cuda_runtime.h>

// Problem constants
#define BB   4
#define CC   256
#define GG   16
#define KF   7      // filter K
#define PP   3
#define HH   56
#define WW   56
#define HW   (HH*WW)          // 3136
#define CR   64               // C / R
#define CPG  16               // C / G
#define KK2  49               // K*K

#define XCH_STRIDE 284        // per-channel stride in sh_x (words); 284%32=28, /4 ok
#define XROW_STRIDE 20        // per-row stride (words), float4 friendly

// Scratch for h = reduce(x): [B][CR][HW] fp32 = 3.2 MB
__device__ float g_h[BB * CR * HW];

// ---------------------------------------------------------------------------
// Kernel 1: h[b][o][p] = sum_c reduce_w[o][c] * x[b][c][p] + reduce_b[o]
// 128 threads, tile 64 px x 64 outputs; thread = 8 outputs x 4 px.
// ---------------------------------------------------------------------------
__global__ __launch_bounds__(128) void reduce_kernel(
    const float* __restrict__ x,
    const float* __restrict__ rw,
    const float* __restrict__ rb)
{
    __shared__ float sx[64 * 64];    // [c][px]
    __shared__ float srw[64 * 64];   // [o][c]

    const int b    = blockIdx.y;
    const int px0  = blockIdx.x * 64;
    const int tid  = threadIdx.x;
    const int quad = tid & 15;       // 4-px quad
    const int o0   = (tid >> 4) * 8; // 8 outputs

    float acc[8][4];
#pragma unroll
    for (int j = 0; j < 8; j++)
#pragma unroll
        for (int p = 0; p < 4; p++) acc[j][p] = 0.f;

    for (int cc0 = 0; cc0 < CC; cc0 += 64) {
        // stage x chunk [64 c][64 px] as float4
        for (int i = tid; i < 1024; i += 128) {
            int c = i >> 4, q = i & 15;
            reinterpret_cast<float4*>(sx + c * 64)[q] =
                reinterpret_cast<const float4*>(x + (b * CC + cc0 + c) * HW + px0)[q];
        }
        // stage weight chunk [64 o][64 c] as float4
        for (int i = tid; i < 1024; i += 128) {
            int o = i >> 4, q = i & 15;
            reinterpret_cast<float4*>(srw + o * 64)[q] =
                reinterpret_cast<const float4*>(rw + o * CC + cc0)[q];
        }
        __syncthreads();

#pragma unroll 4
        for (int c = 0; c < 64; c++) {
            float4 xv = reinterpret_cast<const float4*>(sx + c * 64)[quad];
#pragma unroll
            for (int j = 0; j < 8; j++) {
                float w = srw[(o0 + j) * 64 + c];
                acc[j][0] += w * xv.x;
                acc[j][1] += w * xv.y;
                acc[j][2] += w * xv.z;
                acc[j][3] += w * xv.w;
            }
        }
        __syncthreads();
    }

#pragma unroll
    for (int j = 0; j < 8; j++) {
        float bias = rb[o0 + j];
        float4 v = make_float4(acc[j][0] + bias, acc[j][1] + bias,
                               acc[j][2] + bias, acc[j][3] + bias);
        reinterpret_cast<float4*>(g_h + (b * CR + o0 + j) * HW + px0)[quad] = v;
    }
}

// ---------------------------------------------------------------------------
// Kernel 2: fused span GEMM + involution, shared-traffic-optimized.
// Grid (7,7,B*G), 256 threads, 8x8 output tile per (batch, group).
//  phase1 : stage h tile [64c][64px] + x patch [16ch][14x14 padded]
//  phase2 : kern[49][64px] = sw_g @ h + b.  224 threads: 7 kk per thread,
//           c-loop split in half (2 x 112), partial reduce through sh_k.
//  phase3 : 64 threads: 4 ch x 4 px each, kv row held in registers per kh.
// ---------------------------------------------------------------------------
__global__ __launch_bounds__(256) void invol_kernel(
    const float* __restrict__ x,
    const float* __restrict__ sw,
    const float* __restrict__ sb,
    float* __restrict__ out)
{
    __shared__ float sh_h[64 * 64];              // 16 KB
    __shared__ float sh_k[KK2 * 64];             // 12.25 KB (partials, then kern)
    __shared__ float sh_x[CPG * XCH_STRIDE];     // 17.75 KB

    const int bz  = blockIdx.z;
    const int b   = bz >> 4;
    const int g   = bz & 15;
    const int ty0 = blockIdx.y * 8;
    const int tx0 = blockIdx.x * 8;
    const int tid = threadIdx.x;

    // ---- phase 1: h tile, vectorized ----
    for (int i = tid; i < 1024; i += 256) {
        int c  = i >> 4, q = i & 15;
        int px = q * 4;
        int ly = px >> 3, lx = px & 7;
        reinterpret_cast<float4*>(sh_h + c * 64)[q] =
            *reinterpret_cast<const float4*>(
                g_h + (b * CR + c) * HW + (ty0 + ly) * WW + tx0 + lx);
    }
    // ---- phase 1b: x patch, 16 ch x 14x14 with zero-padded halo ----
    for (int i = tid; i < CPG * 14 * 14; i += 256) {
        int ch = i / 196;
        int r2 = i % 196;
        int r = r2 / 14, cw = r2 % 14;
        int gy = ty0 + r - PP, gx = tx0 + cw - PP;
        float v = 0.f;
        if (gy >= 0 && gy < HH && gx >= 0 && gx < WW)
            v = x[((b * CC + g * CPG + ch) * HH + gy) * WW + gx];
        sh_x[ch * XCH_STRIDE + r * XROW_STRIDE + cw] = v;
    }
    __syncthreads();

    // ---- phase 2: kern GEMM, 7 kk per thread, split-c ----
    const int grp    = tid >> 4;          // 0..15
    const int quad   = tid & 15;
    const bool p2act = (grp < 14);
    const int kkg    = p2act ? (grp % 7) : 0;
    const int chalf  = p2act ? (grp / 7) : 0;

    float acc2[7][4];
#pragma unroll
    for (int j = 0; j < 7; j++)
#pragma unroll
        for (int p = 0; p < 4; p++) acc2[j][p] = 0.f;

    if (p2act) {
        const float* wbase = sw + (g * KK2 + kkg * 7) * CR;
        const int c0 = chalf * 32;
#pragma unroll 2
        for (int c = c0; c < c0 + 32; c++) {
            float4 hv = reinterpret_cast<const float4*>(sh_h + c * 64)[quad];
#pragma unroll
            for (int j = 0; j < 7; j++) {
                float w = __ldg(wbase + j * CR + c);
                acc2[j][0] += w * hv.x;
                acc2[j][1] += w * hv.y;
                acc2[j][2] += w * hv.z;
                acc2[j][3] += w * hv.w;
            }
        }
    }
    // upper half writes partials
    if (p2act && chalf == 1) {
#pragma unroll
        for (int j = 0; j < 7; j++)
            reinterpret_cast<float4*>(sh_k + (kkg * 7 + j) * 64)[quad] =
                make_float4(acc2[j][0], acc2[j][1], acc2[j][2], acc2[j][3]);
    }
    __syncthreads();
    // lower half combines + bias, writes final kern
    if (p2act && chalf == 0) {
#pragma unroll
        for (int j = 0; j < 7; j++) {
            int kk = kkg * 7 + j;
            float4 pp = reinterpret_cast<const float4*>(sh_k + kk * 64)[quad];
            float bias = sb[g * KK2 + kk];
            reinterpret_cast<float4*>(sh_k + kk * 64)[quad] =
                make_float4(acc2[j][0] + pp.x + bias, acc2[j][1] + pp.y + bias,
                            acc2[j][2] + pp.z + bias, acc2[j][3] + pp.w + bias);
        }
    }
    __syncthreads();

    // ---- phase 3: involution, 64 threads: 4 ch x 4 px each ----
    if (tid < 64) {
        const int chq = tid >> 4;        // 0..3 -> channels chq*4 .. chq*4+3
        const int q3  = tid & 15;
        const int ly  = q3 >> 1;
        const int lx  = (q3 & 1) * 4;

        float acc[4][4];
#pragma unroll
        for (int j = 0; j < 4; j++)
#pragma unroll
            for (int p = 0; p < 4; p++) acc[j][p] = 0.f;

#pragma unroll
        for (int kh = 0; kh < KF; kh++) {
            // kv row for this kh, held in registers (7 float4)
            float4 kv[KF];
#pragma unroll
            for (int kw = 0; kw < KF; kw++)
                kv[kw] = reinterpret_cast<const float4*>(sh_k + (kh * KF + kw) * 64)[q3];

#pragma unroll
            for (int j = 0; j < 4; j++) {
                const float* xp = sh_x + (chq * 4 + j) * XCH_STRIDE
                                        + (ly + kh) * XROW_STRIDE + lx;
                float4 xa = *reinterpret_cast<const float4*>(xp);
                float4 xb = *reinterpret_cast<const float4*>(xp + 4);
                float4 xc = *reinterpret_cast<const float4*>(xp + 8);
                float xr[12] = {xa.x, xa.y, xa.z, xa.w,
                                xb.x, xb.y, xb.z, xb.w,
                                xc.x, xc.y, xc.z, xc.w};
#pragma unroll
                for (int kw = 0; kw < KF; kw++) {
                    acc[j][0] += kv[kw].x * xr[kw + 0];
                    acc[j][1] += kv[kw].y * xr[kw + 1];
                    acc[j][2] += kv[kw].z * xr[kw + 2];
                    acc[j][3] += kv[kw].w * xr[kw + 3];
                }
            }
        }

#pragma unroll
        for (int j = 0; j < 4; j++) {
            int ch = chq * 4 + j;
            *reinterpret_cast<float4*>(
                out + ((b * CC + g * CPG + ch) * HH + ty0 + ly) * WW + tx0 + lx) =
                make_float4(acc[j][0], acc[j][1], acc[j][2], acc[j][3]);
        }
    }
}

// ---------------------------------------------------------------------------
extern "C" void kernel_launch(void* const* d_in, const int* in_sizes, int n_in,
                              void* d_out, int out_size)
{
    const float* x  = (const float*)d_in[0];  // (4,256,56,56)
    const float* rw = (const float*)d_in[1];  // (64,256)
    const float* rb = (const float*)d_in[2];  // (64,)
    const float* sw = (const float*)d_in[3];  // (784,64)
    const float* sb = (const float*)d_in[4];  // (784,)
    float* out = (float*)d_out;               // (4,256,56,56)

    reduce_kernel<<<dim3(HW / 64, BB), 128>>>(x, rw, rb);
    invol_kernel<<<dim3(WW / 8, HH / 8, BB * GG), 256>>>(x, sw, sb, out);
}

// round 11
// speedup vs baseline: 2.9400x; 1.1452x over previous
#include <cuda_runtime.h>

// Problem constants
#define BB   4
#define CC   256
#define GG   16
#define KF   7      // filter K
#define PP   3
#define HH   56
#define WW   56
#define HW   (HH*WW)          // 3136
#define CR   64               // C / R
#define CPG  16               // C / G
#define KK2  49               // K*K

#define XCH_STRIDE 284        // per-channel stride in sh_x (words)
#define XROW_STRIDE 20        // per-row stride (words), float4 friendly
#define WSTRIDE 68            // weight row stride in reused sh_k region

// Scratch for h = reduce(x): [B][CR][HW] fp32 = 3.2 MB
__device__ float g_h[BB * CR * HW];

// ---------------------------------------------------------------------------
// Kernel 1: h[b][o][p] = sum_c reduce_w[o][c] * x[b][c][p] + reduce_b[o]
// 128 threads, tile 64 px x 64 outputs; thread = 8 outputs x 4 px.
// ---------------------------------------------------------------------------
__global__ __launch_bounds__(128) void reduce_kernel(
    const float* __restrict__ x,
    const float* __restrict__ rw,
    const float* __restrict__ rb)
{
    __shared__ float sx[64 * 64];    // [c][px]
    __shared__ float srw[64 * 64];   // [o][c]

    const int b    = blockIdx.y;
    const int px0  = blockIdx.x * 64;
    const int tid  = threadIdx.x;
    const int quad = tid & 15;       // 4-px quad
    const int o0   = (tid >> 4) * 8; // 8 outputs

    float acc[8][4];
#pragma unroll
    for (int j = 0; j < 8; j++)
#pragma unroll
        for (int p = 0; p < 4; p++) acc[j][p] = 0.f;

    for (int cc0 = 0; cc0 < CC; cc0 += 64) {
        for (int i = tid; i < 1024; i += 128) {
            int c = i >> 4, q = i & 15;
            reinterpret_cast<float4*>(sx + c * 64)[q] =
                reinterpret_cast<const float4*>(x + (b * CC + cc0 + c) * HW + px0)[q];
        }
        for (int i = tid; i < 1024; i += 128) {
            int o = i >> 4, q = i & 15;
            reinterpret_cast<float4*>(srw + o * 64)[q] =
                reinterpret_cast<const float4*>(rw + o * CC + cc0)[q];
        }
        __syncthreads();

#pragma unroll 4
        for (int c = 0; c < 64; c++) {
            float4 xv = reinterpret_cast<const float4*>(sx + c * 64)[quad];
#pragma unroll
            for (int j = 0; j < 8; j++) {
                float w = srw[(o0 + j) * 64 + c];
                acc[j][0] += w * xv.x;
                acc[j][1] += w * xv.y;
                acc[j][2] += w * xv.z;
                acc[j][3] += w * xv.w;
            }
        }
        __syncthreads();
    }

#pragma unroll
    for (int j = 0; j < 8; j++) {
        float bias = rb[o0 + j];
        float4 v = make_float4(acc[j][0] + bias, acc[j][1] + bias,
                               acc[j][2] + bias, acc[j][3] + bias);
        reinterpret_cast<float4*>(g_h + (b * CR + o0 + j) * HW + px0)[quad] = v;
    }
}

// ---------------------------------------------------------------------------
// Kernel 2: fused span GEMM + involution.
// Grid (7,7,B*G), 256 threads, 8x8 output tile per (batch, group).
//  phase1 : stage h tile [64c][64px], x patch [16ch][14x14 padded],
//           and span_w group slice [49][64] into sh_k (stride 68, reused).
//  phase2 : kern[49][64px] = sw_g @ h + b.  224 threads: 7 kk x 4 px each,
//           c split in half; weights read from shared via broadcast LDS.
//           After the c-loop, sh_k is reused (stride 64) for partials/kern.
//  phase3 : 128 threads: 2 ch x 4 px each, kv row in registers per kh.
// ---------------------------------------------------------------------------
__global__ __launch_bounds__(256, 4) void invol_kernel(
    const float* __restrict__ x,
    const float* __restrict__ sw,
    const float* __restrict__ sb,
    float* __restrict__ out)
{
    __shared__ float sh_h[64 * 64];              // 16 KB
    __shared__ float sh_k[KK2 * WSTRIDE];        // 13.0 KB (weights -> partials -> kern)
    __shared__ float sh_x[CPG * XCH_STRIDE];     // 17.75 KB

    const int bz  = blockIdx.z;
    const int b   = bz >> 4;
    const int g   = bz & 15;
    const int ty0 = blockIdx.y * 8;
    const int tx0 = blockIdx.x * 8;
    const int tid = threadIdx.x;

    // ---- phase 1: h tile ----
    for (int i = tid; i < 1024; i += 256) {
        int c  = i >> 4, q = i & 15;
        int ly = q >> 1, lx = (q & 1) * 4;
        reinterpret_cast<float4*>(sh_h + c * 64)[q] =
            *reinterpret_cast<const float4*>(
                g_h + (b * CR + c) * HW + (ty0 + ly) * WW + tx0 + lx);
    }
    // ---- phase 1a: span_w group slice into sh_k (stride WSTRIDE) ----
    {
        const float* swg = sw + (g * KK2) * CR;
        for (int i = tid; i < KK2 * 16; i += 256) {
            int r = i >> 4, q = i & 15;
            *reinterpret_cast<float4*>(sh_k + r * WSTRIDE + q * 4) =
                *reinterpret_cast<const float4*>(swg + r * CR + q * 4);
        }
    }
    // ---- phase 1b: x patch, 16 ch x 14x14 with zero-padded halo ----
    for (int i = tid; i < CPG * 14 * 14; i += 256) {
        int ch = i / 196;
        int r2 = i % 196;
        int r = r2 / 14, cw = r2 % 14;
        int gy = ty0 + r - PP, gx = tx0 + cw - PP;
        float v = 0.f;
        if (gy >= 0 && gy < HH && gx >= 0 && gx < WW)
            v = x[((b * CC + g * CPG + ch) * HH + gy) * WW + gx];
        sh_x[ch * XCH_STRIDE + r * XROW_STRIDE + cw] = v;
    }
    __syncthreads();

    // ---- phase 2: kern GEMM, 7 kk per thread, split-c, shared weights ----
    const int grp    = tid >> 4;          // 0..15
    const int quad   = tid & 15;
    const bool p2act = (grp < 14);
    const int kkg    = p2act ? (grp % 7) : 0;
    const int chalf  = p2act ? (grp / 7) : 0;

    float acc2[7][4];
#pragma unroll
    for (int j = 0; j < 7; j++)
#pragma unroll
        for (int p = 0; p < 4; p++) acc2[j][p] = 0.f;

    if (p2act) {
        const int c0 = chalf * 32;
        const float* wbase = sh_k + (kkg * 7) * WSTRIDE;
#pragma unroll 2
        for (int c4 = 0; c4 < 32; c4 += 4) {
            int c = c0 + c4;
            float4 hv0 = reinterpret_cast<const float4*>(sh_h + (c + 0) * 64)[quad];
            float4 hv1 = reinterpret_cast<const float4*>(sh_h + (c + 1) * 64)[quad];
            float4 hv2 = reinterpret_cast<const float4*>(sh_h + (c + 2) * 64)[quad];
            float4 hv3 = reinterpret_cast<const float4*>(sh_h + (c + 3) * 64)[quad];
#pragma unroll
            for (int j = 0; j < 7; j++) {
                float4 w = *reinterpret_cast<const float4*>(wbase + j * WSTRIDE + c);
                acc2[j][0] += w.x * hv0.x; acc2[j][1] += w.x * hv0.y;
                acc2[j][2] += w.x * hv0.z; acc2[j][3] += w.x * hv0.w;
                acc2[j][0] += w.y * hv1.x; acc2[j][1] += w.y * hv1.y;
                acc2[j][2] += w.y * hv1.z; acc2[j][3] += w.y * hv1.w;
                acc2[j][0] += w.z * hv2.x; acc2[j][1] += w.z * hv2.y;
                acc2[j][2] += w.z * hv2.z; acc2[j][3] += w.z * hv2.w;
                acc2[j][0] += w.w * hv3.x; acc2[j][1] += w.w * hv3.y;
                acc2[j][2] += w.w * hv3.z; acc2[j][3] += w.w * hv3.w;
            }
        }
    }
    // weights are dead from here; sh_k region reused (stride 64) for partials/kern
    __syncthreads();
    if (p2act && chalf == 1) {
#pragma unroll
        for (int j = 0; j < 7; j++)
            reinterpret_cast<float4*>(sh_k + (kkg * 7 + j) * 64)[quad] =
                make_float4(acc2[j][0], acc2[j][1], acc2[j][2], acc2[j][3]);
    }
    __syncthreads();
    if (p2act && chalf == 0) {
#pragma unroll
        for (int j = 0; j < 7; j++) {
            int kk = kkg * 7 + j;
            float4 pp = reinterpret_cast<const float4*>(sh_k + kk * 64)[quad];
            float bias = sb[g * KK2 + kk];
            reinterpret_cast<float4*>(sh_k + kk * 64)[quad] =
                make_float4(acc2[j][0] + pp.x + bias, acc2[j][1] + pp.y + bias,
                            acc2[j][2] + pp.z + bias, acc2[j][3] + pp.w + bias);
        }
    }
    __syncthreads();

    // ---- phase 3: involution, 128 threads: 2 ch x 4 px each ----
    if (tid < 128) {
        const int chp = tid >> 4;        // 0..7 -> channels chp*2, chp*2+1
        const int q3  = tid & 15;
        const int ly  = q3 >> 1;
        const int lx  = (q3 & 1) * 4;

        float acc[2][4];
#pragma unroll
        for (int j = 0; j < 2; j++)
#pragma unroll
            for (int p = 0; p < 4; p++) acc[j][p] = 0.f;

#pragma unroll
        for (int kh = 0; kh < KF; kh++) {
            float4 kv[KF];
#pragma unroll
            for (int kw = 0; kw < KF; kw++)
                kv[kw] = reinterpret_cast<const float4*>(sh_k + (kh * KF + kw) * 64)[q3];

#pragma unroll
            for (int j = 0; j < 2; j++) {
                const float* xp = sh_x + (chp * 2 + j) * XCH_STRIDE
                                        + (ly + kh) * XROW_STRIDE + lx;
                float4 xa = *reinterpret_cast<const float4*>(xp);
                float4 xb = *reinterpret_cast<const float4*>(xp + 4);
                float4 xc = *reinterpret_cast<const float4*>(xp + 8);
                float xr[12] = {xa.x, xa.y, xa.z, xa.w,
                                xb.x, xb.y, xb.z, xb.w,
                                xc.x, xc.y, xc.z, xc.w};
#pragma unroll
                for (int kw = 0; kw < KF; kw++) {
                    acc[j][0] += kv[kw].x * xr[kw + 0];
                    acc[j][1] += kv[kw].y * xr[kw + 1];
                    acc[j][2] += kv[kw].z * xr[kw + 2];
                    acc[j][3] += kv[kw].w * xr[kw + 3];
                }
            }
        }

#pragma unroll
        for (int j = 0; j < 2; j++) {
            int ch = chp * 2 + j;
            *reinterpret_cast<float4*>(
                out + ((b * CC + g * CPG + ch) * HH + ty0 + ly) * WW + tx0 + lx) =
                make_float4(acc[j][0], acc[j][1], acc[j][2], acc[j][3]);
        }
    }
}

// ---------------------------------------------------------------------------
extern "C" void kernel_launch(void* const* d_in, const int* in_sizes, int n_in,
                              void* d_out, int out_size)
{
    const float* x  = (const float*)d_in[0];  // (4,256,56,56)
    const float* rw = (const float*)d_in[1];  // (64,256)
    const float* rb = (const float*)d_in[2];  // (64,)
    const float* sw = (const float*)d_in[3];  // (784,64)
    const float* sb = (const float*)d_in[4];  // (784,)
    float* out = (float*)d_out;               // (4,256,56,56)

    reduce_kernel<<<dim3(HW / 64, BB), 128>>>(x, rw, rb);
    invol_kernel<<<dim3(WW / 8, HH / 8, BB * GG), 256>>>(x, sw, sb, out);
}